// round 5
// baseline (speedup 1.0000x reference)
#include <cuda_runtime.h>

// Shapes (fixed for this problem)
#define B_  2
#define T_  2048
#define H_  8
#define D_  64
#define M_  64
#define C_  32                 // chunk length (timesteps per block)
#define NC_ (T_ / C_)          // 64 chunks per (b,h)
#define RS  512                // row stride in floats between consecutive t (H*D)
#define PAD 68                 // smem row stride in floats (272B, 16B-aligned, conflict-free)
#define PAD4 (PAD / 4)         // 17 float4s per row
#define NSEG 4                 // time segments per chunk (8 steps each)

// Per-(b,h,chunk) column sums of fmap(k): [B*H*NC][D]
__device__ float g_chunksum[B_ * H_ * NC_ * D_];
// Publish flags, one per (b,h,chunk). Reset by k_zero each launch.
__device__ int   g_flag[B_ * H_ * NC_];

__device__ __forceinline__ float fmap(float x) {
    // elu(x) + 1 (alpha=1): x>0 -> x+1 ; x<=0 -> exp(x)
    return x > 0.0f ? x + 1.0f : __expf(x);
}
__device__ __forceinline__ float4 fmap4(float4 a) {
    return make_float4(fmap(a.x), fmap(a.y), fmap(a.z), fmap(a.w));
}

// ---------------------------------------------------------------------------
// Reset flags (graph node #1; must precede the main kernel each replay)
// ---------------------------------------------------------------------------
__global__ void k_zero() {
    const int i = blockIdx.x * blockDim.x + threadIdx.x;
    if (i < B_ * H_ * NC_) g_flag[i] = 0;
}

// ---------------------------------------------------------------------------
// Fused single-pass kernel. grid = B*H*NC = 1024 blocks, 256 threads.
// All blocks resident in one wave (launch_bounds(256,8): regs<=32,
// smem 22.9KB <= 28.5KB) -> publish-then-wait on lower block ids is safe.
// ---------------------------------------------------------------------------
__global__ __launch_bounds__(256, 8) void k_fused(const float* __restrict__ q,
                                                  const float* __restrict__ k,
                                                  const float* __restrict__ v,
                                                  float* __restrict__ out) {
    __shared__ float loc_s[C_ * PAD];      // fmap(k) -> local inclusive time-scan (in place)
    __shared__ float qf_s[C_ * PAD];       // fmap(q)
    __shared__ float segsum[NSEG * 64];    // per-segment column sums
    __shared__ float carr[64];             // cross-chunk carry per d
    __shared__ float Sg[8 * C_], Dg[8 * C_], Kg[8 * C_], Qg[8 * C_];
    __shared__ float scal[C_];

    float4* loc4 = (float4*)loc_s;
    float4* qf4  = (float4*)qf_s;
    float4* ca4  = (float4*)carr;

    const int bc  = blockIdx.x;
    const int c   = bc & (NC_ - 1);        // chunk index within (b,h)
    const int bh  = bc >> 6;               // b*H + h
    const int tid = threadIdx.x;

    const int   h    = bh & (H_ - 1);
    const int   b    = bh >> 3;
    const size_t base = (((size_t)b * T_ + (size_t)c * C_) * H_ + h) * D_;

    // ---- Phase A: coalesced vector load of k,q -> fmap -> smem ----
    #pragma unroll
    for (int it = 0; it < 2; it++) {
        const int i  = tid + it * 256;         // 0..511
        const int t  = i >> 4;
        const int dv = i & 15;
        const size_t g = base + (size_t)t * RS + dv * 4;
        loc4[t * PAD4 + dv] = fmap4(*(const float4*)(k + g));
        qf4[t * PAD4 + dv]  = fmap4(*(const float4*)(q + g));
    }
    __syncthreads();

    // ---- B1: local inclusive time-scan IN PLACE (256 threads = 64 d x 4 seg) ----
    {
        const int d = tid & 63, seg = tid >> 6;
        float run = 0.0f;
        #pragma unroll
        for (int i = 0; i < C_ / NSEG; i++) {
            const int t = seg * (C_ / NSEG) + i;
            run += loc_s[t * PAD + d];
            loc_s[t * PAD + d] = run;
        }
        segsum[seg * 64 + d] = run;
    }
    __syncthreads();

    // ---- Publish chunk column-sums (tid<64) || B2 offsets (tid>=64, segs 1..3) ----
    if (tid < 64) {
        const float tot = segsum[tid] + segsum[64 + tid] + segsum[128 + tid] + segsum[192 + tid];
        g_chunksum[bc * D_ + tid] = tot;
        __threadfence();                   // release: sums visible before flag
    } else {
        const int d = tid & 63, seg = tid >> 6;   // seg in 1..3
        float off = segsum[d];
        for (int s = 1; s < seg; s++) off += segsum[s * 64 + d];
        #pragma unroll
        for (int i = 0; i < C_ / NSEG; i++) {
            const int t = seg * (C_ / NSEG) + i;
            loc_s[t * PAD + d] += off;
        }
    }
    __syncthreads();

    // ---- Set own flag; parallel-poll prior chunks' flags ----
    volatile int* vf = (volatile int*)g_flag;
    if (tid == 0) vf[bc] = 1;              // all writers fenced above
    if (tid < c) {
        while (vf[(bh << 6) + tid] == 0) __nanosleep(64);
    }
    __threadfence();                       // acquire side
    __syncthreads();

    // ---- Carry: sum prior chunk sums (tid<64, L2 reads, independent) ----
    if (tid < 64) {
        float run = 0.0f;
        const float* cs = &g_chunksum[(bh << 6) * D_ + tid];
        #pragma unroll 4
        for (int cc = 0; cc < c; cc++) run += __ldcg(cs + cc * D_);
        carr[tid] = run;
    }
    __syncthreads();

    // ---- Phase C: thread (t = tid&31, dg = tid>>5) handles 8 d's ----
    {
        const int t = tid & 31, dg = tid >> 5;
        const int b4 = t * PAD4 + dg * 2;
        float dcum = 0.0f, S = 0.0f, den = 0.0f, qs = 0.0f;
        #pragma unroll
        for (int j = 0; j < 2; j++) {
            const float4 lv = loc4[b4 + j];
            float4 pv = make_float4(0.f, 0.f, 0.f, 0.f);
            if (t > 0) pv = loc4[b4 - PAD4 + j];
            const float4 qf = qf4[b4 + j];
            const float4 cv = ca4[dg * 2 + j];     // warp-uniform -> broadcast

            den += qf.x * (lv.x + cv.x) + qf.y * (lv.y + cv.y)
                 + qf.z * (lv.z + cv.z) + qf.w * (lv.w + cv.w);

            dcum += lv.x - pv.x;  S += qf.x * dcum;
            dcum += lv.y - pv.y;  S += qf.y * dcum;
            dcum += lv.z - pv.z;  S += qf.z * dcum;
            dcum += lv.w - pv.w;  S += qf.w * dcum;
            qs   += qf.x + qf.y + qf.z + qf.w;
        }
        Sg[dg * C_ + t] = S;
        Dg[dg * C_ + t] = den;
        Kg[dg * C_ + t] = dcum;
        Qg[dg * C_ + t] = qs;
    }
    __syncthreads();

    // ---- Combine the 8 d-groups: S = sum_g (S_g + ktot_{<g} * qsum_g) ----
    if (tid < C_) {
        const int t = tid;
        float kpre = 0.0f, S = 0.0f, den = 0.0f;
        #pragma unroll
        for (int g = 0; g < 8; g++) {
            S    += Sg[g * C_ + t] + kpre * Qg[g * C_ + t];
            den  += Dg[g * C_ + t];
            kpre += Kg[g * C_ + t];
        }
        scal[t] = S / den;
    }
    __syncthreads();

    // ---- Phase D: out = v * scale (coalesced float4) ----
    #pragma unroll
    for (int it = 0; it < 2; it++) {
        const int i  = tid + it * 256;
        const int t  = i >> 4;
        const int mv = i & 15;
        const size_t g = base + (size_t)t * RS + mv * 4;
        float4 vv = *(const float4*)(v + g);
        const float s = scal[t];
        vv.x *= s; vv.y *= s; vv.z *= s; vv.w *= s;
        *(float4*)(out + g) = vv;
    }
}

extern "C" void kernel_launch(void* const* d_in, const int* in_sizes, int n_in,
                              void* d_out, int out_size) {
    const float* q = (const float*)d_in[0];
    const float* k = (const float*)d_in[1];
    const float* v = (const float*)d_in[2];
    float* out = (float*)d_out;

    k_zero<<<(B_ * H_ * NC_ + 255) / 256, 256>>>();
    k_fused<<<B_ * H_ * NC_, 256>>>(q, k, v, out);   // 1024 blocks
}

// round 6
// speedup vs baseline: 2.0467x; 2.0467x over previous
#include <cuda_runtime.h>

// Shapes (fixed for this problem)
#define B_  2
#define T_  2048
#define H_  8
#define D_  64
#define M_  64
#define C_  32                 // chunk length (timesteps per block)
#define NC_ (T_ / C_)          // 64 chunks per (b,h)
#define RS  512                // row stride in floats between consecutive t (H*D)
#define PAD 68                 // smem row stride in floats (272B, 16B-aligned, conflict-free)
#define PAD4 (PAD / 4)         // 17 float4s per row
#define NSEG 4                 // time segments per chunk (8 steps each)

// Per-(b,h,chunk) column sums of fmap(k): [B*H*NC][D]
__device__ float g_chunksum[B_ * H_ * NC_ * D_];

__device__ __forceinline__ float fmap(float x) {
    // elu(x) + 1 (alpha=1): x>0 -> x+1 ; x<=0 -> exp(x)
    return x > 0.0f ? x + 1.0f : __expf(x);
}
__device__ __forceinline__ float4 fmap4(float4 a) {
    return make_float4(fmap(a.x), fmap(a.y), fmap(a.z), fmap(a.w));
}
__device__ __forceinline__ float4 add4(float4 a, float4 b) {
    return make_float4(a.x + b.x, a.y + b.y, a.z + b.z, a.w + b.w);
}

// ---------------------------------------------------------------------------
// Kernel 1: per-chunk (32 steps) column sums of fmap(k). grid = 1024, 256 thr.
// ---------------------------------------------------------------------------
__global__ __launch_bounds__(256) void k_chunksum(const float* __restrict__ k) {
    __shared__ float4 red[16][16];          // [tg][dv]
    const int bc  = blockIdx.x;
    const int c   = bc & (NC_ - 1);
    const int bh  = bc >> 6;
    const int h   = bh & (H_ - 1);
    const int b   = bh >> 3;
    const int tid = threadIdx.x;
    const int tg  = tid >> 4;               // 0..15
    const int dv  = tid & 15;               // float4 index over d

    const size_t base = (((size_t)b * T_ + (size_t)c * C_) * H_ + h) * D_;

    float4 s = make_float4(0.f, 0.f, 0.f, 0.f);
    #pragma unroll
    for (int i = 0; i < 2; i++) {
        const int t = tg + i * 16;
        s = add4(s, fmap4(*(const float4*)(k + base + (size_t)t * RS + dv * 4)));
    }
    red[tg][dv] = s;
    __syncthreads();

    if (tid < 16) {
        float4 acc = red[0][tid];
        #pragma unroll
        for (int t = 1; t < 16; t++) acc = add4(acc, red[t][tid]);
        *(float4*)(&g_chunksum[bc * D_ + tid * 4]) = acc;
    }
}

// ---------------------------------------------------------------------------
// Kernel 2: main. grid = 1024 blocks, 256 threads, smem ~24KB -> 8 blocks/SM.
// ---------------------------------------------------------------------------
__global__ __launch_bounds__(256) void k_main(const float* __restrict__ q,
                                              const float* __restrict__ k,
                                              const float* __restrict__ v,
                                              float* __restrict__ out) {
    __shared__ float loc_s[C_ * PAD];      // fmap(k) -> local inclusive time-scan (in place)
    __shared__ float qf_s[C_ * PAD];       // fmap(q)
    __shared__ float segsum[NSEG * 64];    // per-segment column sums
    __shared__ float carp[4 * 64];         // carry partials (4-way split over chunks)
    __shared__ float carr[64];             // cross-chunk carry per d
    __shared__ float Sg[8 * C_], Dg[8 * C_], Kg[8 * C_], Qg[8 * C_];
    __shared__ float scal[C_];

    float4* loc4 = (float4*)loc_s;
    float4* qf4  = (float4*)qf_s;
    float4* ca4  = (float4*)carr;

    const int bc  = blockIdx.x;
    const int c   = bc & (NC_ - 1);
    const int bh  = bc >> 6;
    const int h   = bh & (H_ - 1);
    const int b   = bh >> 3;
    const int tid = threadIdx.x;

    const size_t base = (((size_t)b * T_ + (size_t)c * C_) * H_ + h) * D_;

    // ---- Phase A: coalesced vector load of k,q -> fmap -> smem (STS.128) ----
    #pragma unroll
    for (int it = 0; it < 2; it++) {
        const int i  = tid + it * 256;         // 0..511
        const int t  = i >> 4;
        const int dv = i & 15;
        const size_t g = base + (size_t)t * RS + dv * 4;
        loc4[t * PAD4 + dv] = fmap4(*(const float4*)(k + g));
        qf4[t * PAD4 + dv]  = fmap4(*(const float4*)(q + g));
    }

    // ---- Carry partials: 256 threads, 4-way chunk split, overlapped with A ----
    {
        const int d = tid & 63, p = tid >> 6;
        const int lo = p * 16;
        const int hi = (c < lo + 16) ? c : (lo + 16);
        float run = 0.0f;
        const float* cs = &g_chunksum[((bh << 6)) * D_ + d];
        #pragma unroll 4
        for (int cc = lo; cc < hi; cc++) run += cs[cc * D_];
        carp[p * 64 + d] = run;
    }
    __syncthreads();

    // ---- B1: local inclusive time-scan IN PLACE (256 threads = 64 d x 4 seg) ----
    {
        const int d = tid & 63, seg = tid >> 6;
        float run = 0.0f;
        #pragma unroll
        for (int i = 0; i < C_ / NSEG; i++) {
            const int t = seg * (C_ / NSEG) + i;
            run += loc_s[t * PAD + d];
            loc_s[t * PAD + d] = run;
        }
        segsum[seg * 64 + d] = run;
    }
    __syncthreads();

    // ---- B2 offsets (segs 1..3, 192 threads) || carry reduce (tid<64) ----
    if (tid < 64) {
        carr[tid] = carp[tid] + carp[64 + tid] + carp[128 + tid] + carp[192 + tid];
    } else {
        const int d = tid & 63, seg = tid >> 6;   // 1..3
        float off = segsum[d];
        for (int s = 1; s < seg; s++) off += segsum[s * 64 + d];
        #pragma unroll
        for (int i = 0; i < C_ / NSEG; i++) {
            const int t = seg * (C_ / NSEG) + i;
            loc_s[t * PAD + d] += off;
        }
    }
    __syncthreads();

    // ---- Phase C: thread (t = tid&31, dg = tid>>5) handles 8 d's (2x LDS.128) ----
    {
        const int t = tid & 31, dg = tid >> 5;
        const int b4 = t * PAD4 + dg * 2;
        float dcum = 0.0f, S = 0.0f, den = 0.0f, qs = 0.0f;
        #pragma unroll
        for (int j = 0; j < 2; j++) {
            const float4 lv = loc4[b4 + j];
            float4 pv = make_float4(0.f, 0.f, 0.f, 0.f);
            if (t > 0) pv = loc4[b4 - PAD4 + j];
            const float4 qf = qf4[b4 + j];
            const float4 cv = ca4[dg * 2 + j];     // warp-uniform -> broadcast

            den += qf.x * (lv.x + cv.x) + qf.y * (lv.y + cv.y)
                 + qf.z * (lv.z + cv.z) + qf.w * (lv.w + cv.w);

            dcum += lv.x - pv.x;  S += qf.x * dcum;
            dcum += lv.y - pv.y;  S += qf.y * dcum;
            dcum += lv.z - pv.z;  S += qf.z * dcum;
            dcum += lv.w - pv.w;  S += qf.w * dcum;
            qs   += qf.x + qf.y + qf.z + qf.w;
        }
        Sg[dg * C_ + t] = S;
        Dg[dg * C_ + t] = den;
        Kg[dg * C_ + t] = dcum;
        Qg[dg * C_ + t] = qs;
    }
    __syncthreads();

    // ---- Combine the 8 d-groups: S = sum_g (S_g + ktot_{<g} * qsum_g) ----
    if (tid < C_) {
        const int t = tid;
        float kpre = 0.0f, S = 0.0f, den = 0.0f;
        #pragma unroll
        for (int g = 0; g < 8; g++) {
            S    += Sg[g * C_ + t] + kpre * Qg[g * C_ + t];
            den  += Dg[g * C_ + t];
            kpre += Kg[g * C_ + t];
        }
        scal[t] = S / den;
    }
    __syncthreads();

    // ---- Phase D: out = v * scale (coalesced float4) ----
    #pragma unroll
    for (int it = 0; it < 2; it++) {
        const int i  = tid + it * 256;
        const int t  = i >> 4;
        const int mv = i & 15;
        const size_t g = base + (size_t)t * RS + mv * 4;
        float4 vv = *(const float4*)(v + g);
        const float s = scal[t];
        vv.x *= s; vv.y *= s; vv.z *= s; vv.w *= s;
        *(float4*)(out + g) = vv;
    }
}

extern "C" void kernel_launch(void* const* d_in, const int* in_sizes, int n_in,
                              void* d_out, int out_size) {
    const float* q = (const float*)d_in[0];
    const float* k = (const float*)d_in[1];
    const float* v = (const float*)d_in[2];
    float* out = (float*)d_out;

    const int nblocks = B_ * H_ * NC_;     // 1024
    k_chunksum<<<nblocks, 256>>>(k);
    k_main<<<nblocks, 256>>>(q, k, v, out);
}